// round 10
// baseline (speedup 1.0000x reference)
#include <cuda_runtime.h>
#include <math.h>
#include <stdint.h>

// Problem constants
#define S_ 8192
#define D_ 2048
#define H_ 64
#define E_ 64
#define L_ 64

#define NPART 512          // colsum partial blocks (16 rows each)
#define BM 64
#define BN 128
#define KC 32
#define NCH (D_ / KC)      // 64
#define RS 40              // smem row stride in bf16 (80 B, conflict-free ldsm)
#define NSTAGE 4

// dynamic smem stage layout (bytes)
#define AHI_OFF 0
#define ALO_OFF 5120
#define BHI_OFF 10240
#define BLO_OFF 20480
#define STAGE_BYTES 30720
#define SMEM_DYN (NSTAGE * STAGE_BYTES)   // 122880

// Static device scratch
__device__ __align__(16) float g_vpart[NPART][D_];
__device__ __align__(16) float g_v[D_];
__device__ float g_gate[2];
__device__ int   g_idx[2];
__device__ __align__(16) uint16_t g_xhi[S_][D_];       // 32 MB
__device__ __align__(16) uint16_t g_xlo[S_][D_];       // 32 MB
__device__ __align__(16) uint16_t g_whi[2 * L_][D_];   // 512 KB
__device__ __align__(16) uint16_t g_wlo[2 * L_][D_];

// ===========================================================================
// helpers
// ===========================================================================
__device__ __forceinline__ uint32_t smem_u32(const void* p) {
    uint32_t a;
    asm("{ .reg .u64 t; cvta.to.shared.u64 t, %1; cvt.u32.u64 %0, t; }"
        : "=r"(a) : "l"(p));
    return a;
}

__device__ __forceinline__ void cp16(uint32_t dst, const void* src) {
    asm volatile("cp.async.cg.shared.global [%0], [%1], 16;"
                 :: "r"(dst), "l"(src) : "memory");
}
#define CP_COMMIT() asm volatile("cp.async.commit_group;" ::: "memory")
#define CP_WAIT(n)  asm volatile("cp.async.wait_group %0;" :: "n"(n) : "memory")

// bf16 hi/lo split of 2 floats: hi = rn(f), lo = rn(f - hi), packed bf16x2
__device__ __forceinline__ void cvt_split(float f0, float f1, uint32_t& hi, uint32_t& lo) {
    uint32_t h;
    asm("cvt.rn.bf16x2.f32 %0, %1, %2;" : "=r"(h) : "f"(f1), "f"(f0));
    const float l0 = f0 - __uint_as_float(h << 16);
    const float l1 = f1 - __uint_as_float(h & 0xFFFF0000u);
    uint32_t l;
    asm("cvt.rn.bf16x2.f32 %0, %1, %2;" : "=r"(l) : "f"(l1), "f"(l0));
    hi = h; lo = l;
}

__device__ __forceinline__ void ldsm4(uint32_t* r, uint32_t addr) {
    asm volatile("ldmatrix.sync.aligned.m8n8.x4.shared.b16 {%0,%1,%2,%3}, [%4];"
                 : "=r"(r[0]), "=r"(r[1]), "=r"(r[2]), "=r"(r[3]) : "r"(addr));
}

__device__ __forceinline__ void mma_bf16(float* c, const uint32_t* a, const uint32_t* b) {
    asm volatile("mma.sync.aligned.m16n8k16.row.col.f32.bf16.bf16.f32 "
                 "{%0,%1,%2,%3}, {%4,%5,%6,%7}, {%8,%9}, {%0,%1,%2,%3};"
                 : "+f"(c[0]), "+f"(c[1]), "+f"(c[2]), "+f"(c[3])
                 : "r"(a[0]), "r"(a[1]), "r"(a[2]), "r"(a[3]), "r"(b[0]), "r"(b[1]));
}

__device__ __forceinline__ float gelu_exact(float v) {
    return 0.5f * v * (1.f + erff(v * 0.70710678118654752440f));
}

// ===========================================================================
// Kernel 1: fused weighted column-sum partials + bf16 hi/lo split of x.
// 512 blocks x 16 rows.
// ===========================================================================
__global__ void __launch_bounds__(256) k_colsum_split(const float* __restrict__ x,
                                                      const float* __restrict__ wout) {
    __shared__ float ws[16];
    const int b = blockIdx.x, t = threadIdx.x;
    const int row0 = b * 16;
    if (t < 16) ws[t] = wout[row0 + t];
    __syncthreads();

    const int d0 = t * 8;
    float acc[8];
#pragma unroll
    for (int i = 0; i < 8; i++) acc[i] = 0.f;
    const float* xp = x + (size_t)row0 * D_ + d0;
#pragma unroll 4
    for (int r = 0; r < 16; r++) {
        const float w = ws[r];
        const float4 a = *(const float4*)(xp);
        const float4 c = *(const float4*)(xp + 4);
        acc[0] = fmaf(w, a.x, acc[0]); acc[1] = fmaf(w, a.y, acc[1]);
        acc[2] = fmaf(w, a.z, acc[2]); acc[3] = fmaf(w, a.w, acc[3]);
        acc[4] = fmaf(w, c.x, acc[4]); acc[5] = fmaf(w, c.y, acc[5]);
        acc[6] = fmaf(w, c.z, acc[6]); acc[7] = fmaf(w, c.w, acc[7]);
        uint4 hi, lo;
        cvt_split(a.x, a.y, hi.x, lo.x);
        cvt_split(a.z, a.w, hi.y, lo.y);
        cvt_split(c.x, c.y, hi.z, lo.z);
        cvt_split(c.z, c.w, hi.w, lo.w);
        *(uint4*)&g_xhi[row0 + r][d0] = hi;
        *(uint4*)&g_xlo[row0 + r][d0] = lo;
        xp += D_;
    }
#pragma unroll
    for (int i = 0; i < 8; i++) g_vpart[b][d0 + i] = acc[i];
}

// ===========================================================================
// Kernel 2a: v[d] = sum_b vpart[b][d]
// ===========================================================================
__global__ void __launch_bounds__(256) k_vreduce() {
    const int d = blockIdx.x * 256 + threadIdx.x;
    float s = 0.f;
#pragma unroll 8
    for (int b = 0; b < NPART; b++) s += g_vpart[b][d];
    g_v[d] = s;
}

// ===========================================================================
// Kernel 2b: fused gate: u = Wg_in@v; scores = Wg_lin@u; top-2; softmax.
// ===========================================================================
__global__ void __launch_bounds__(512) k_gate(const float* __restrict__ Wg_in,
                                              const float* __restrict__ Wg_lin) {
    __shared__ float v[D_];
    __shared__ float u[H_];
    __shared__ float sc[E_];
    const int t = threadIdx.x;
    for (int d = t; d < D_; d += 512) v[d] = g_v[d];
    __syncthreads();

    const int wid = t >> 5, lane = t & 31;
#pragma unroll
    for (int jj = 0; jj < 4; jj++) {
        const int j = wid * 4 + jj;
        const float* wr = Wg_in + (size_t)j * D_;
        float s = 0.f;
#pragma unroll
        for (int i = 0; i < 16; i++) {
            const float4 w = *(const float4*)(wr + i * 128 + lane * 4);
            const float4 vv = *(const float4*)(&v[i * 128 + lane * 4]);
            s += w.x * vv.x + w.y * vv.y + w.z * vv.z + w.w * vv.w;
        }
#pragma unroll
        for (int off = 16; off; off >>= 1) s += __shfl_down_sync(0xffffffffu, s, off);
        if (lane == 0) u[j] = s;
    }
    __syncthreads();

    if (t < E_) {
        float s = 0.f;
#pragma unroll
        for (int j = 0; j < H_; j++) s = fmaf(Wg_lin[t * H_ + j], u[j], s);
        sc[t] = s;
    }
    __syncthreads();

    if (t == 0) {
        int i0 = 0;
        for (int e = 1; e < E_; e++) if (sc[e] > sc[i0]) i0 = e;
        int i1 = (i0 == 0) ? 1 : 0;
        for (int e = 0; e < E_; e++) {
            if (e == i0 || e == i1) continue;
            if (sc[e] > sc[i1]) i1 = e;
        }
        const float e1 = expf(sc[i1] - sc[i0]);
        const float inv = 1.f / (1.f + e1);
        g_gate[0] = inv; g_gate[1] = e1 * inv;
        g_idx[0] = i0; g_idx[1] = i1;
    }
}

// ===========================================================================
// Kernel 2c: split the TWO selected experts' weights (grid 128 x 256).
// ===========================================================================
__global__ void __launch_bounds__(256) k_wsplit(const float* __restrict__ We) {
    const int r = blockIdx.x;
    const int t = threadIdx.x;
    const int e = (r < 64) ? g_idx[0] : g_idx[1];
    const float* src = We + ((size_t)e * L_ + (r & 63)) * D_ + t * 8;
    const float4 f0 = *(const float4*)(src);
    const float4 f1 = *(const float4*)(src + 4);
    uint4 hi, lo;
    cvt_split(f0.x, f0.y, hi.x, lo.x);
    cvt_split(f0.z, f0.w, hi.y, lo.y);
    cvt_split(f1.x, f1.y, hi.z, lo.z);
    cvt_split(f1.z, f1.w, hi.w, lo.w);
    *(uint4*)&g_whi[r][t * 8] = hi;
    *(uint4*)&g_wlo[r][t * 8] = lo;
}

// ===========================================================================
// Kernel 3: HMMA expert GEMM on pre-split bf16, cp.async 4-stage pipeline.
// 512 threads, 16 warps in 4x4 grid; warp tile 16x32 via m16n8k16.
// Fused normalize+GELU+combine epilogue.
// ===========================================================================
__global__ void __launch_bounds__(512) k_expert(float* __restrict__ out) {
    extern __shared__ char dsm[];
    const uint32_t sbase = smem_u32(dsm);

    const int t = threadIdx.x;
    const int wid = t >> 5, lane = t & 31;
    const int row0 = blockIdx.x * BM;

    // ---- cp.async load mapping (16B segments) ----
    // A: 64 rows x 4 segs = 256 items -> threads 0..255, hi+lo each
    const bool doA = t < 256;
    const int arow = (t & 255) >> 2, aseg = t & 3;
    const uint16_t* gAhi = &g_xhi[row0 + arow][aseg * 8];
    const uint16_t* gAlo = &g_xlo[row0 + arow][aseg * 8];
    const uint32_t adst = (uint32_t)(arow * RS * 2 + aseg * 16);
    // B: 128 rows x 4 segs = 512 items -> 1 per thread, hi+lo each
    const int brow = t >> 2, bseg = t & 3;
    const uint16_t* gBhi = &g_whi[brow][bseg * 8];
    const uint16_t* gBlo = &g_wlo[brow][bseg * 8];
    const uint32_t bdst = (uint32_t)(brow * RS * 2 + bseg * 16);

    // ---- fragment mapping: warp (warp_m, warp_n), tile 16x32 ----
    const int warp_m = wid & 3, warp_n = wid >> 2;
    const int m_base = warp_m * 16, n_base = warp_n * 32;
    const int a_row = m_base + (lane & 15);
    const int a_k = (lane >> 4) << 3;
    const int b_row = n_base + ((lane >> 4) << 3) + (lane & 7);
    const int b_k = ((lane >> 3) & 1) << 3;
    const uint32_t fa = (uint32_t)(a_row * RS + a_k) * 2;
    const uint32_t fb = (uint32_t)(b_row * RS + b_k) * 2;

    float c[4][4];
#pragma unroll
    for (int nt = 0; nt < 4; nt++)
#pragma unroll
        for (int r = 0; r < 4; r++) c[nt][r] = 0.f;

    // ---- prologue: prefetch stages 0..2 ----
#pragma unroll
    for (int s = 0; s < NSTAGE - 1; s++) {
        const uint32_t sb = sbase + s * STAGE_BYTES;
        if (doA) {
            cp16(sb + AHI_OFF + adst, gAhi + s * KC);
            cp16(sb + ALO_OFF + adst, gAlo + s * KC);
        }
        cp16(sb + BHI_OFF + bdst, gBhi + s * KC);
        cp16(sb + BLO_OFF + bdst, gBlo + s * KC);
        CP_COMMIT();
    }

#pragma unroll 1
    for (int ch = 0; ch < NCH; ++ch) {
        CP_WAIT(2);
        __syncthreads();

        const uint32_t tb = sbase + (ch & (NSTAGE - 1)) * STAGE_BYTES;
#pragma unroll
        for (int ks = 0; ks < 2; ks++) {
            const uint32_t kb = ks * 32;   // 16 bf16 = 32 bytes
            uint32_t ahi[4], alo[4], bhi[2][4], blo[2][4];
            ldsm4(ahi, tb + AHI_OFF + fa + kb);
            ldsm4(alo, tb + ALO_OFF + fa + kb);
#pragma unroll
            for (int nn = 0; nn < 2; nn++) {
                ldsm4(bhi[nn], tb + BHI_OFF + fb + nn * (16 * RS * 2) + kb);
                ldsm4(blo[nn], tb + BLO_OFF + fb + nn * (16 * RS * 2) + kb);
            }
            // term-outermost: 4 independent MMAs between accumulator reuses
#pragma unroll
            for (int nt = 0; nt < 4; nt++)
                mma_bf16(c[nt], ahi, &bhi[nt >> 1][(nt & 1) * 2]);
#pragma unroll
            for (int nt = 0; nt < 4; nt++)
                mma_bf16(c[nt], alo, &bhi[nt >> 1][(nt & 1) * 2]);
#pragma unroll
            for (int nt = 0; nt < 4; nt++)
                mma_bf16(c[nt], ahi, &blo[nt >> 1][(nt & 1) * 2]);
        }

        const int pf = ch + NSTAGE - 1;
        if (pf < NCH) {
            const uint32_t sb = sbase + (pf & (NSTAGE - 1)) * STAGE_BYTES;
            if (doA) {
                cp16(sb + AHI_OFF + adst, gAhi + pf * KC);
                cp16(sb + ALO_OFF + adst, gAlo + pf * KC);
            }
            cp16(sb + BHI_OFF + bdst, gBhi + pf * KC);
            cp16(sb + BLO_OFF + bdst, gBlo + pf * KC);
        }
        CP_COMMIT();
    }

    CP_WAIT(0);
    __syncthreads();

    // ---- stage C into smem (overlays stage space) ----
    float (*C)[BN] = (float (*)[BN])dsm;
#pragma unroll
    for (int nt = 0; nt < 4; nt++) {
        const int r0 = m_base + (lane >> 2);
        const int c0 = n_base + nt * 8 + 2 * (lane & 3);
        *(float2*)&C[r0][c0]     = make_float2(c[nt][0], c[nt][1]);
        *(float2*)&C[r0 + 8][c0] = make_float2(c[nt][2], c[nt][3]);
    }
    __syncthreads();

    // ---- epilogue: per-row L2 norm per expert half, GELU, gated combine ----
    const float g0 = g_gate[0], g1 = g_gate[1];
#pragma unroll
    for (int r = 0; r < 4; r++) {
        const int row = wid * 4 + r;
        const float z0a = C[row][lane];
        const float z0b = C[row][lane + 32];
        const float z1a = C[row][64 + lane];
        const float z1b = C[row][96 + lane];
        float ss0 = z0a * z0a + z0b * z0b;
        float ss1 = z1a * z1a + z1b * z1b;
#pragma unroll
        for (int off = 16; off; off >>= 1) {
            ss0 += __shfl_xor_sync(0xffffffffu, ss0, off);
            ss1 += __shfl_xor_sync(0xffffffffu, ss1, off);
        }
        const float inv0 = 1.f / fmaxf(sqrtf(ss0), 1e-12f);
        const float inv1 = 1.f / fmaxf(sqrtf(ss1), 1e-12f);
        float* orow = out + (size_t)(row0 + row) * L_;
        orow[lane]      = g0 * gelu_exact(z0a * inv0) + g1 * gelu_exact(z1a * inv1);
        orow[lane + 32] = g0 * gelu_exact(z0b * inv0) + g1 * gelu_exact(z1b * inv1);
    }
}

// ===========================================================================
extern "C" void kernel_launch(void* const* d_in, const int* in_sizes, int n_in,
                              void* d_out, int out_size) {
    const float* x      = (const float*)d_in[0];
    const float* Wg_in  = (const float*)d_in[1];
    const float* Wg_lin = (const float*)d_in[2];
    const float* Wg_out = (const float*)d_in[3];
    const float* We     = (const float*)d_in[4];
    float* out = (float*)d_out;

    cudaFuncSetAttribute(k_expert, cudaFuncAttributeMaxDynamicSharedMemorySize, SMEM_DYN);

    k_colsum_split<<<NPART, 256>>>(x, Wg_out);
    k_vreduce<<<8, 256>>>();
    k_gate<<<1, 512>>>(Wg_in, Wg_lin);
    k_wsplit<<<128, 256>>>(We);
    k_expert<<<S_ / BM, 512, SMEM_DYN>>>(out);
}

// round 11
// speedup vs baseline: 1.0407x; 1.0407x over previous
#include <cuda_runtime.h>
#include <math.h>
#include <stdint.h>

// Problem constants
#define S_ 8192
#define D_ 2048
#define H_ 64
#define E_ 64
#define L_ 64

#define NPART 256          // colsum partial blocks (32 rows each)
#define BM 64
#define BN 128
#define KC 32
#define NCH (D_ / KC)      // 64
#define RS 40              // smem row stride in bf16 (80 B, conflict-free ldsm)
#define NSTAGE 4

// dynamic smem stage layout (bytes)
#define AHI_OFF 0
#define ALO_OFF 5120
#define BHI_OFF 10240
#define BLO_OFF 20480
#define STAGE_BYTES 30720
#define SMEM_DYN (NSTAGE * STAGE_BYTES)   // 122880

// Static device scratch
__device__ __align__(16) float g_vpart[NPART][D_];
__device__ __align__(16) float g_v[D_];
__device__ float g_gate[2];
__device__ int   g_idx[2];
__device__ __align__(16) uint16_t g_xhi[S_][D_];       // 32 MB
__device__ __align__(16) uint16_t g_xlo[S_][D_];       // 32 MB
__device__ __align__(16) uint16_t g_whi[2 * L_][D_];   // 512 KB
__device__ __align__(16) uint16_t g_wlo[2 * L_][D_];

// ===========================================================================
// helpers
// ===========================================================================
__device__ __forceinline__ uint32_t smem_u32(const void* p) {
    uint32_t a;
    asm("{ .reg .u64 t; cvta.to.shared.u64 t, %1; cvt.u32.u64 %0, t; }"
        : "=r"(a) : "l"(p));
    return a;
}

__device__ __forceinline__ void cp16(uint32_t dst, const void* src) {
    asm volatile("cp.async.cg.shared.global [%0], [%1], 16;"
                 :: "r"(dst), "l"(src) : "memory");
}
#define CP_COMMIT() asm volatile("cp.async.commit_group;" ::: "memory")
#define CP_WAIT(n)  asm volatile("cp.async.wait_group %0;" :: "n"(n) : "memory")

// bf16 hi/lo split of 2 floats: hi = rn(f), lo = rn(f - hi), packed bf16x2
__device__ __forceinline__ void cvt_split(float f0, float f1, uint32_t& hi, uint32_t& lo) {
    uint32_t h;
    asm("cvt.rn.bf16x2.f32 %0, %1, %2;" : "=r"(h) : "f"(f1), "f"(f0));
    const float l0 = f0 - __uint_as_float(h << 16);
    const float l1 = f1 - __uint_as_float(h & 0xFFFF0000u);
    uint32_t l;
    asm("cvt.rn.bf16x2.f32 %0, %1, %2;" : "=r"(l) : "f"(l1), "f"(l0));
    hi = h; lo = l;
}

__device__ __forceinline__ void ldsm4(uint32_t* r, uint32_t addr) {
    asm volatile("ldmatrix.sync.aligned.m8n8.x4.shared.b16 {%0,%1,%2,%3}, [%4];"
                 : "=r"(r[0]), "=r"(r[1]), "=r"(r[2]), "=r"(r[3]) : "r"(addr));
}

__device__ __forceinline__ void mma_bf16(float* c, const uint32_t* a, const uint32_t* b) {
    asm volatile("mma.sync.aligned.m16n8k16.row.col.f32.bf16.bf16.f32 "
                 "{%0,%1,%2,%3}, {%4,%5,%6,%7}, {%8,%9}, {%0,%1,%2,%3};"
                 : "+f"(c[0]), "+f"(c[1]), "+f"(c[2]), "+f"(c[3])
                 : "r"(a[0]), "r"(a[1]), "r"(a[2]), "r"(a[3]), "r"(b[0]), "r"(b[1]));
}

__device__ __forceinline__ float gelu_exact(float v) {
    return 0.5f * v * (1.f + erff(v * 0.70710678118654752440f));
}

// ===========================================================================
// Kernel 1: fused weighted column-sum partials + bf16 hi/lo split of x.
// 256 blocks x 32 rows.
// ===========================================================================
__global__ void __launch_bounds__(256) k_colsum_split(const float* __restrict__ x,
                                                      const float* __restrict__ wout) {
    __shared__ float ws[32];
    const int b = blockIdx.x, t = threadIdx.x;
    const int row0 = b * 32;
    if (t < 32) ws[t] = wout[row0 + t];
    __syncthreads();

    const int d0 = t * 8;
    float acc[8];
#pragma unroll
    for (int i = 0; i < 8; i++) acc[i] = 0.f;
    const float* xp = x + (size_t)row0 * D_ + d0;
#pragma unroll 4
    for (int r = 0; r < 32; r++) {
        const float w = ws[r];
        const float4 a = *(const float4*)(xp);
        const float4 c = *(const float4*)(xp + 4);
        acc[0] = fmaf(w, a.x, acc[0]); acc[1] = fmaf(w, a.y, acc[1]);
        acc[2] = fmaf(w, a.z, acc[2]); acc[3] = fmaf(w, a.w, acc[3]);
        acc[4] = fmaf(w, c.x, acc[4]); acc[5] = fmaf(w, c.y, acc[5]);
        acc[6] = fmaf(w, c.z, acc[6]); acc[7] = fmaf(w, c.w, acc[7]);
        uint4 hi, lo;
        cvt_split(a.x, a.y, hi.x, lo.x);
        cvt_split(a.z, a.w, hi.y, lo.y);
        cvt_split(c.x, c.y, hi.z, lo.z);
        cvt_split(c.z, c.w, hi.w, lo.w);
        *(uint4*)&g_xhi[row0 + r][d0] = hi;
        *(uint4*)&g_xlo[row0 + r][d0] = lo;
        xp += D_;
    }
#pragma unroll
    for (int i = 0; i < 8; i++) g_vpart[b][d0 + i] = acc[i];
}

// ===========================================================================
// Kernel 2a: v[d] = sum_b vpart[b][d]
// ===========================================================================
__global__ void __launch_bounds__(256) k_vreduce() {
    const int d = blockIdx.x * 256 + threadIdx.x;
    float s = 0.f;
#pragma unroll 8
    for (int b = 0; b < NPART; b++) s += g_vpart[b][d];
    g_v[d] = s;
}

// ===========================================================================
// Kernel 2b: fused gate: u = Wg_in@v; scores = Wg_lin@u; top-2; softmax.
// ===========================================================================
__global__ void __launch_bounds__(512) k_gate(const float* __restrict__ Wg_in,
                                              const float* __restrict__ Wg_lin) {
    __shared__ float v[D_];
    __shared__ float u[H_];
    __shared__ float sc[E_];
    const int t = threadIdx.x;
    for (int d = t; d < D_; d += 512) v[d] = g_v[d];
    __syncthreads();

    const int wid = t >> 5, lane = t & 31;
#pragma unroll
    for (int jj = 0; jj < 4; jj++) {
        const int j = wid * 4 + jj;
        const float* wr = Wg_in + (size_t)j * D_;
        float s = 0.f;
#pragma unroll
        for (int i = 0; i < 16; i++) {
            const float4 w = *(const float4*)(wr + i * 128 + lane * 4);
            const float4 vv = *(const float4*)(&v[i * 128 + lane * 4]);
            s += w.x * vv.x + w.y * vv.y + w.z * vv.z + w.w * vv.w;
        }
#pragma unroll
        for (int off = 16; off; off >>= 1) s += __shfl_down_sync(0xffffffffu, s, off);
        if (lane == 0) u[j] = s;
    }
    __syncthreads();

    if (t < E_) {
        float s = 0.f;
#pragma unroll
        for (int j = 0; j < H_; j++) s = fmaf(Wg_lin[t * H_ + j], u[j], s);
        sc[t] = s;
    }
    __syncthreads();

    if (t == 0) {
        int i0 = 0;
        for (int e = 1; e < E_; e++) if (sc[e] > sc[i0]) i0 = e;
        int i1 = (i0 == 0) ? 1 : 0;
        for (int e = 0; e < E_; e++) {
            if (e == i0 || e == i1) continue;
            if (sc[e] > sc[i1]) i1 = e;
        }
        const float e1 = expf(sc[i1] - sc[i0]);
        const float inv = 1.f / (1.f + e1);
        g_gate[0] = inv; g_gate[1] = e1 * inv;
        g_idx[0] = i0; g_idx[1] = i1;
    }
}

// ===========================================================================
// Kernel 2c: split the TWO selected experts' weights (grid 128 x 256).
// ===========================================================================
__global__ void __launch_bounds__(256) k_wsplit(const float* __restrict__ We) {
    const int r = blockIdx.x;
    const int t = threadIdx.x;
    const int e = (r < 64) ? g_idx[0] : g_idx[1];
    const float* src = We + ((size_t)e * L_ + (r & 63)) * D_ + t * 8;
    const float4 f0 = *(const float4*)(src);
    const float4 f1 = *(const float4*)(src + 4);
    uint4 hi, lo;
    cvt_split(f0.x, f0.y, hi.x, lo.x);
    cvt_split(f0.z, f0.w, hi.y, lo.y);
    cvt_split(f1.x, f1.y, hi.z, lo.z);
    cvt_split(f1.z, f1.w, hi.w, lo.w);
    *(uint4*)&g_whi[r][t * 8] = hi;
    *(uint4*)&g_wlo[r][t * 8] = lo;
}

// ===========================================================================
// Kernel 3: HMMA expert GEMM on pre-split bf16, cp.async 4-stage pipeline,
// within-chunk fragment double-buffering (ks=1 LDSMs issued before ks=0 MMAs),
// term-outermost MMA issue, fused normalize+GELU+combine epilogue.
//   CTA: 64 rows x 128 cols; 8 warps 2x4; warp = 32x32 via m16n8k16.
// ===========================================================================
__global__ void __launch_bounds__(256) k_expert(float* __restrict__ out) {
    extern __shared__ char dsm[];
    const uint32_t sbase = smem_u32(dsm);

    const int t = threadIdx.x;
    const int wid = t >> 5, lane = t & 31;
    const int row0 = blockIdx.x * BM;

    // ---- cp.async load mapping (16B segments) ----
    const int arow = t >> 2, aseg = t & 3;
    const uint16_t* gAhi = &g_xhi[row0 + arow][aseg * 8];
    const uint16_t* gAlo = &g_xlo[row0 + arow][aseg * 8];
    const uint32_t adst = (uint32_t)(arow * RS * 2 + aseg * 16);
    const uint16_t* gBhi[2]; const uint16_t* gBlo[2]; uint32_t bdst[2];
#pragma unroll
    for (int j = 0; j < 2; j++) {
        const int idx = j * 256 + t;
        const int br = idx >> 2, bs = idx & 3;
        gBhi[j] = &g_whi[br][bs * 8];
        gBlo[j] = &g_wlo[br][bs * 8];
        bdst[j] = (uint32_t)(br * RS * 2 + bs * 16);
    }

    // ---- fragment mapping ----
    const int warp_m = wid & 1, warp_n = wid >> 1;
    const int m_base = warp_m * 32, n_base = warp_n * 32;
    const int a_row = m_base + (lane & 15);
    const int a_k = (lane >> 4) << 3;
    const int b_row = n_base + ((lane >> 4) << 3) + (lane & 7);
    const int b_k = ((lane >> 3) & 1) << 3;
    const uint32_t fa = (uint32_t)(a_row * RS + a_k) * 2;
    const uint32_t fb = (uint32_t)(b_row * RS + b_k) * 2;

    float c[2][4][4];
#pragma unroll
    for (int mt = 0; mt < 2; mt++)
#pragma unroll
        for (int nt = 0; nt < 4; nt++)
#pragma unroll
            for (int r = 0; r < 4; r++) c[mt][nt][r] = 0.f;

    // ---- prologue: prefetch stages 0..2 ----
#pragma unroll
    for (int s = 0; s < NSTAGE - 1; s++) {
        const uint32_t sb = sbase + s * STAGE_BYTES;
        cp16(sb + AHI_OFF + adst, gAhi + s * KC);
        cp16(sb + ALO_OFF + adst, gAlo + s * KC);
#pragma unroll
        for (int j = 0; j < 2; j++) {
            cp16(sb + BHI_OFF + bdst[j], gBhi[j] + s * KC);
            cp16(sb + BLO_OFF + bdst[j], gBlo[j] + s * KC);
        }
        CP_COMMIT();
    }

    // double-buffered fragment sets: [set][mt|nn][4]
    uint32_t ahi[2][2][4], alo[2][2][4], bhi[2][2][4], blo[2][2][4];

#pragma unroll 1
    for (int ch = 0; ch < NCH; ++ch) {
        CP_WAIT(2);
        __syncthreads();

        const uint32_t tb = sbase + (ch & (NSTAGE - 1)) * STAGE_BYTES;

        // load ks=0 fragments
#pragma unroll
        for (int mt = 0; mt < 2; mt++) {
            ldsm4(ahi[0][mt], tb + AHI_OFF + fa + mt * (16 * RS * 2));
            ldsm4(alo[0][mt], tb + ALO_OFF + fa + mt * (16 * RS * 2));
        }
#pragma unroll
        for (int nn = 0; nn < 2; nn++) {
            ldsm4(bhi[0][nn], tb + BHI_OFF + fb + nn * (16 * RS * 2));
            ldsm4(blo[0][nn], tb + BLO_OFF + fb + nn * (16 * RS * 2));
        }

        // issue next chunk's cp.async into the stage just freed (stage ch-1)
        const int pf = ch + NSTAGE - 1;
        if (pf < NCH) {
            const uint32_t sb = sbase + (pf & (NSTAGE - 1)) * STAGE_BYTES;
            cp16(sb + AHI_OFF + adst, gAhi + pf * KC);
            cp16(sb + ALO_OFF + adst, gAlo + pf * KC);
#pragma unroll
            for (int j = 0; j < 2; j++) {
                cp16(sb + BHI_OFF + bdst[j], gBhi[j] + pf * KC);
                cp16(sb + BLO_OFF + bdst[j], gBlo[j] + pf * KC);
            }
        }
        CP_COMMIT();

#pragma unroll
        for (int ks = 0; ks < 2; ks++) {
            if (ks == 0) {
                // issue ks=1 LDSMs; latency hides under ks=0 MMAs below
#pragma unroll
                for (int mt = 0; mt < 2; mt++) {
                    ldsm4(ahi[1][mt], tb + AHI_OFF + fa + mt * (16 * RS * 2) + 32);
                    ldsm4(alo[1][mt], tb + ALO_OFF + fa + mt * (16 * RS * 2) + 32);
                }
#pragma unroll
                for (int nn = 0; nn < 2; nn++) {
                    ldsm4(bhi[1][nn], tb + BHI_OFF + fb + nn * (16 * RS * 2) + 32);
                    ldsm4(blo[1][nn], tb + BLO_OFF + fb + nn * (16 * RS * 2) + 32);
                }
            }
            // term-outermost: 8 independent MMAs between accumulator reuses
#pragma unroll
            for (int mt = 0; mt < 2; mt++)
#pragma unroll
                for (int nt = 0; nt < 4; nt++)
                    mma_bf16(c[mt][nt], ahi[ks][mt], &bhi[ks][nt >> 1][(nt & 1) * 2]);
#pragma unroll
            for (int mt = 0; mt < 2; mt++)
#pragma unroll
                for (int nt = 0; nt < 4; nt++)
                    mma_bf16(c[mt][nt], alo[ks][mt], &bhi[ks][nt >> 1][(nt & 1) * 2]);
#pragma unroll
            for (int mt = 0; mt < 2; mt++)
#pragma unroll
                for (int nt = 0; nt < 4; nt++)
                    mma_bf16(c[mt][nt], ahi[ks][mt], &blo[ks][nt >> 1][(nt & 1) * 2]);
        }
    }

    CP_WAIT(0);
    __syncthreads();

    // ---- stage C into smem (overlays stage space) ----
    float (*C)[BN] = (float (*)[BN])dsm;
#pragma unroll
    for (int mt = 0; mt < 2; mt++)
#pragma unroll
        for (int nt = 0; nt < 4; nt++) {
            const int r0 = m_base + mt * 16 + (lane >> 2);
            const int c0 = n_base + nt * 8 + 2 * (lane & 3);
            *(float2*)&C[r0][c0]     = make_float2(c[mt][nt][0], c[mt][nt][1]);
            *(float2*)&C[r0 + 8][c0] = make_float2(c[mt][nt][2], c[mt][nt][3]);
        }
    __syncthreads();

    // ---- epilogue: per-row L2 norm per expert half, GELU, gated combine ----
    const float g0 = g_gate[0], g1 = g_gate[1];
#pragma unroll
    for (int r = 0; r < 8; r++) {
        const int row = wid * 8 + r;
        const float z0a = C[row][lane];
        const float z0b = C[row][lane + 32];
        const float z1a = C[row][64 + lane];
        const float z1b = C[row][96 + lane];
        float ss0 = z0a * z0a + z0b * z0b;
        float ss1 = z1a * z1a + z1b * z1b;
#pragma unroll
        for (int off = 16; off; off >>= 1) {
            ss0 += __shfl_xor_sync(0xffffffffu, ss0, off);
            ss1 += __shfl_xor_sync(0xffffffffu, ss1, off);
        }
        const float inv0 = 1.f / fmaxf(sqrtf(ss0), 1e-12f);
        const float inv1 = 1.f / fmaxf(sqrtf(ss1), 1e-12f);
        float* orow = out + (size_t)(row0 + row) * L_;
        orow[lane]      = g0 * gelu_exact(z0a * inv0) + g1 * gelu_exact(z1a * inv1);
        orow[lane + 32] = g0 * gelu_exact(z0b * inv0) + g1 * gelu_exact(z1b * inv1);
    }
}

// ===========================================================================
extern "C" void kernel_launch(void* const* d_in, const int* in_sizes, int n_in,
                              void* d_out, int out_size) {
    const float* x      = (const float*)d_in[0];
    const float* Wg_in  = (const float*)d_in[1];
    const float* Wg_lin = (const float*)d_in[2];
    const float* Wg_out = (const float*)d_in[3];
    const float* We     = (const float*)d_in[4];
    float* out = (float*)d_out;

    cudaFuncSetAttribute(k_expert, cudaFuncAttributeMaxDynamicSharedMemorySize, SMEM_DYN);

    k_colsum_split<<<NPART, 256>>>(x, Wg_out);
    k_vreduce<<<8, 256>>>();
    k_gate<<<1, 512>>>(Wg_in, Wg_lin);
    k_wsplit<<<128, 256>>>(We);
    k_expert<<<S_ / BM, 256, SMEM_DYN>>>(out);
}

// round 12
// speedup vs baseline: 1.0409x; 1.0003x over previous
#include <cuda_runtime.h>
#include <math.h>
#include <stdint.h>

// Problem constants
#define S_ 8192
#define D_ 2048
#define H_ 64
#define E_ 64
#define L_ 64

#define NPART 256          // colsum partial blocks (32 rows each)
#define BM 64
#define BN 128
#define KC 32
#define NCH (D_ / KC)      // 64
#define NKK (D_ / 16)      // 128 k-steps of 16
#define RS 40              // smem row stride in bf16 (80 B, conflict-free ldsm)
#define NSTAGE 8

// dynamic smem stage layout (bytes): A only (hi + lo)
#define AHI_OFF 0
#define ALO_OFF 5120
#define STAGE_BYTES 10240
#define SMEM_DYN (NSTAGE * STAGE_BYTES)   // 81920 (>= 32KB C overlay)

// Static device scratch
__device__ __align__(16) float g_vpart[NPART][D_];
__device__ __align__(16) float g_v[D_];
__device__ float g_gate[2];
__device__ int   g_idx[2];
__device__ __align__(16) uint16_t g_xhi[S_][D_];   // 32 MB
__device__ __align__(16) uint16_t g_xlo[S_][D_];   // 32 MB
// B in MMA-fragment layout: [kk 128][warp_n 4][hl 2][nn 2][lane 32] x uint4
__device__ uint4 g_wfrag[NKK * 4 * 2 * 2 * 32];    // 512 KB

__device__ __forceinline__ int wf_idx(int kk, int wn, int hl, int nn) {
    return ((((kk << 2) + wn) * 2 + hl) * 2 + nn) << 5;
}

// ===========================================================================
// helpers
// ===========================================================================
__device__ __forceinline__ uint32_t smem_u32(const void* p) {
    uint32_t a;
    asm("{ .reg .u64 t; cvta.to.shared.u64 t, %1; cvt.u32.u64 %0, t; }"
        : "=r"(a) : "l"(p));
    return a;
}

__device__ __forceinline__ void cp16(uint32_t dst, const void* src) {
    asm volatile("cp.async.cg.shared.global [%0], [%1], 16;"
                 :: "r"(dst), "l"(src) : "memory");
}
#define CP_COMMIT() asm volatile("cp.async.commit_group;" ::: "memory")
#define CP_WAIT(n)  asm volatile("cp.async.wait_group %0;" :: "n"(n) : "memory")

// bf16 hi/lo split of 2 floats: hi = rn(f), lo = rn(f - hi), packed bf16x2
// (lower k index in the low half)
__device__ __forceinline__ void cvt_split(float f0, float f1, uint32_t& hi, uint32_t& lo) {
    uint32_t h;
    asm("cvt.rn.bf16x2.f32 %0, %1, %2;" : "=r"(h) : "f"(f1), "f"(f0));
    const float l0 = f0 - __uint_as_float(h << 16);
    const float l1 = f1 - __uint_as_float(h & 0xFFFF0000u);
    uint32_t l;
    asm("cvt.rn.bf16x2.f32 %0, %1, %2;" : "=r"(l) : "f"(l1), "f"(l0));
    hi = h; lo = l;
}

__device__ __forceinline__ void ldsm4(uint32_t* r, uint32_t addr) {
    asm volatile("ldmatrix.sync.aligned.m8n8.x4.shared.b16 {%0,%1,%2,%3}, [%4];"
                 : "=r"(r[0]), "=r"(r[1]), "=r"(r[2]), "=r"(r[3]) : "r"(addr));
}

__device__ __forceinline__ void mma_bf16(float* c, const uint32_t* a, const uint32_t* b) {
    asm volatile("mma.sync.aligned.m16n8k16.row.col.f32.bf16.bf16.f32 "
                 "{%0,%1,%2,%3}, {%4,%5,%6,%7}, {%8,%9}, {%0,%1,%2,%3};"
                 : "+f"(c[0]), "+f"(c[1]), "+f"(c[2]), "+f"(c[3])
                 : "r"(a[0]), "r"(a[1]), "r"(a[2]), "r"(a[3]), "r"(b[0]), "r"(b[1]));
}

__device__ __forceinline__ float gelu_exact(float v) {
    return 0.5f * v * (1.f + erff(v * 0.70710678118654752440f));
}

// ===========================================================================
// Kernel 1: fused weighted column-sum partials + bf16 hi/lo split of x.
// 256 blocks x 32 rows.
// ===========================================================================
__global__ void __launch_bounds__(256) k_colsum_split(const float* __restrict__ x,
                                                      const float* __restrict__ wout) {
    __shared__ float ws[32];
    const int b = blockIdx.x, t = threadIdx.x;
    const int row0 = b * 32;
    if (t < 32) ws[t] = wout[row0 + t];
    __syncthreads();

    const int d0 = t * 8;
    float acc[8];
#pragma unroll
    for (int i = 0; i < 8; i++) acc[i] = 0.f;
    const float* xp = x + (size_t)row0 * D_ + d0;
#pragma unroll 4
    for (int r = 0; r < 32; r++) {
        const float w = ws[r];
        const float4 a = *(const float4*)(xp);
        const float4 c = *(const float4*)(xp + 4);
        acc[0] = fmaf(w, a.x, acc[0]); acc[1] = fmaf(w, a.y, acc[1]);
        acc[2] = fmaf(w, a.z, acc[2]); acc[3] = fmaf(w, a.w, acc[3]);
        acc[4] = fmaf(w, c.x, acc[4]); acc[5] = fmaf(w, c.y, acc[5]);
        acc[6] = fmaf(w, c.z, acc[6]); acc[7] = fmaf(w, c.w, acc[7]);
        uint4 hi, lo;
        cvt_split(a.x, a.y, hi.x, lo.x);
        cvt_split(a.z, a.w, hi.y, lo.y);
        cvt_split(c.x, c.y, hi.z, lo.z);
        cvt_split(c.z, c.w, hi.w, lo.w);
        *(uint4*)&g_xhi[row0 + r][d0] = hi;
        *(uint4*)&g_xlo[row0 + r][d0] = lo;
        xp += D_;
    }
#pragma unroll
    for (int i = 0; i < 8; i++) g_vpart[b][d0 + i] = acc[i];
}

// ===========================================================================
// Kernel 2a: v[d] = sum_b vpart[b][d]
// ===========================================================================
__global__ void __launch_bounds__(256) k_vreduce() {
    const int d = blockIdx.x * 256 + threadIdx.x;
    float s = 0.f;
#pragma unroll 8
    for (int b = 0; b < NPART; b++) s += g_vpart[b][d];
    g_v[d] = s;
}

// ===========================================================================
// Kernel 2b: fused gate: u = Wg_in@v; scores = Wg_lin@u; top-2; softmax.
// ===========================================================================
__global__ void __launch_bounds__(512) k_gate(const float* __restrict__ Wg_in,
                                              const float* __restrict__ Wg_lin) {
    __shared__ float v[D_];
    __shared__ float u[H_];
    __shared__ float sc[E_];
    const int t = threadIdx.x;
    for (int d = t; d < D_; d += 512) v[d] = g_v[d];
    __syncthreads();

    const int wid = t >> 5, lane = t & 31;
#pragma unroll
    for (int jj = 0; jj < 4; jj++) {
        const int j = wid * 4 + jj;
        const float* wr = Wg_in + (size_t)j * D_;
        float s = 0.f;
#pragma unroll
        for (int i = 0; i < 16; i++) {
            const float4 w = *(const float4*)(wr + i * 128 + lane * 4);
            const float4 vv = *(const float4*)(&v[i * 128 + lane * 4]);
            s += w.x * vv.x + w.y * vv.y + w.z * vv.z + w.w * vv.w;
        }
#pragma unroll
        for (int off = 16; off; off >>= 1) s += __shfl_down_sync(0xffffffffu, s, off);
        if (lane == 0) u[j] = s;
    }
    __syncthreads();

    if (t < E_) {
        float s = 0.f;
#pragma unroll
        for (int j = 0; j < H_; j++) s = fmaf(Wg_lin[t * H_ + j], u[j], s);
        sc[t] = s;
    }
    __syncthreads();

    if (t == 0) {
        int i0 = 0;
        for (int e = 1; e < E_; e++) if (sc[e] > sc[i0]) i0 = e;
        int i1 = (i0 == 0) ? 1 : 0;
        for (int e = 0; e < E_; e++) {
            if (e == i0 || e == i1) continue;
            if (sc[e] > sc[i1]) i1 = e;
        }
        const float e1 = expf(sc[i1] - sc[i0]);
        const float inv = 1.f / (1.f + e1);
        g_gate[0] = inv; g_gate[1] = e1 * inv;
        g_idx[0] = i0; g_idx[1] = i1;
    }
}

// ===========================================================================
// Kernel 2c: split the two selected experts' weights DIRECTLY into MMA
// fragment layout. Work item = (kk, nt32, nn, lane); each thread produces
// one uint4 for hi and one for lo (two n8 tiles x {k-lo, k-hi} reg pairs).
// Fragment semantics match ldmatrix m8n8.x4: thread l holds rows l>>2,
// cols 2(l&3), 2(l&3)+1 (+8 for the second reg).
// grid 128 x 256.
// ===========================================================================
__global__ void __launch_bounds__(256) k_wsplit(const float* __restrict__ We) {
    const int item = blockIdx.x * 256 + threadIdx.x;   // 0..32767
    const int lane = item & 31;
    const int nn   = (item >> 5) & 1;
    const int nt32 = (item >> 6) & 3;
    const int kk   = item >> 8;                         // 0..127

    uint4 hi, lo;
#pragma unroll
    for (int j = 0; j < 2; j++) {
        const int n8t = nt32 * 4 + nn * 2 + j;          // 0..15
        const int e = g_idx[n8t >> 3];
        const int nrow = (n8t * 8 + (lane >> 2)) & 63;
        const float* src = We + ((size_t)e * L_ + nrow) * D_ + kk * 16 + 2 * (lane & 3);
        uint32_t h0, l0, h1, l1;
        cvt_split(src[0], src[1], h0, l0);
        cvt_split(src[8], src[9], h1, l1);
        if (j == 0) { hi.x = h0; hi.y = h1; lo.x = l0; lo.y = l1; }
        else        { hi.z = h0; hi.w = h1; lo.z = l0; lo.w = l1; }
    }
    g_wfrag[wf_idx(kk, nt32, 0, nn) + lane] = hi;
    g_wfrag[wf_idx(kk, nt32, 1, nn) + lane] = lo;
}

// ===========================================================================
// Kernel 3: HMMA expert GEMM. A (pre-split bf16) via cp.async 8-stage smem
// pipeline + LDSM; B fragments loaded straight from global (L2-resident,
// fragment-ordered) into a depth-1 register pipeline. Term-outermost MMA
// issue; fused normalize+GELU+combine epilogue.
//   CTA: 64 rows x 128 cols; 8 warps 2x4; warp = 32x32 via m16n8k16.
// ===========================================================================
__global__ void __launch_bounds__(256) k_expert(float* __restrict__ out) {
    extern __shared__ char dsm[];
    const uint32_t sbase = smem_u32(dsm);

    const int t = threadIdx.x;
    const int wid = t >> 5, lane = t & 31;
    const int row0 = blockIdx.x * BM;

    // ---- cp.async load mapping for A (16B segments; 64 rows x 4 segs) ----
    const int arow = t >> 2, aseg = t & 3;
    const uint16_t* gAhi = &g_xhi[row0 + arow][aseg * 8];
    const uint16_t* gAlo = &g_xlo[row0 + arow][aseg * 8];
    const uint32_t adst = (uint32_t)(arow * RS * 2 + aseg * 16);

    // ---- fragment mapping ----
    const int warp_m = wid & 1, warp_n = wid >> 1;
    const int m_base = warp_m * 32, n_base = warp_n * 32;
    const int a_row = m_base + (lane & 15);
    const int a_k = (lane >> 4) << 3;
    const uint32_t fa = (uint32_t)(a_row * RS + a_k) * 2;

    float c[2][4][4];
#pragma unroll
    for (int mt = 0; mt < 2; mt++)
#pragma unroll
        for (int nt = 0; nt < 4; nt++)
#pragma unroll
            for (int r = 0; r < 4; r++) c[mt][nt][r] = 0.f;

    // ---- prologue: prefetch A stages 0..NSTAGE-2 ----
#pragma unroll
    for (int s = 0; s < NSTAGE - 1; s++) {
        const uint32_t sb = sbase + s * STAGE_BYTES;
        cp16(sb + AHI_OFF + adst, gAhi + s * KC);
        cp16(sb + ALO_OFF + adst, gAlo + s * KC);
        CP_COMMIT();
    }

    // ---- B register pipeline: bfr[parity][hl][nn][4] ----
    uint32_t bfr[2][2][2][4];
#pragma unroll
    for (int hl = 0; hl < 2; hl++)
#pragma unroll
        for (int nn = 0; nn < 2; nn++)
            *(uint4*)bfr[0][hl][nn] = g_wfrag[wf_idx(0, warp_n, hl, nn) + lane];

#pragma unroll 1
    for (int ch = 0; ch < NCH; ++ch) {
        CP_WAIT(NSTAGE - 2);
        __syncthreads();

        const uint32_t tb = sbase + (ch & (NSTAGE - 1)) * STAGE_BYTES;

        // issue next A chunk into the stage just freed
        const int pf = ch + NSTAGE - 1;
        if (pf < NCH) {
            const uint32_t sb = sbase + (pf & (NSTAGE - 1)) * STAGE_BYTES;
            cp16(sb + AHI_OFF + adst, gAhi + pf * KC);
            cp16(sb + ALO_OFF + adst, gAlo + pf * KC);
        }
        CP_COMMIT();

#pragma unroll
        for (int ks = 0; ks < 2; ks++) {
            const int kk = ch * 2 + ks;
            // prefetch next k-step's B fragments (hidden under MMAs)
            if (kk + 1 < NKK) {
#pragma unroll
                for (int hl = 0; hl < 2; hl++)
#pragma unroll
                    for (int nn = 0; nn < 2; nn++)
                        *(uint4*)bfr[ks ^ 1][hl][nn] =
                            g_wfrag[wf_idx(kk + 1, warp_n, hl, nn) + lane];
            }
            // A fragments for this k-step
            uint32_t ahi[2][4], alo[2][4];
#pragma unroll
            for (int mt = 0; mt < 2; mt++) {
                ldsm4(ahi[mt], tb + AHI_OFF + fa + mt * (16 * RS * 2) + ks * 32);
                ldsm4(alo[mt], tb + ALO_OFF + fa + mt * (16 * RS * 2) + ks * 32);
            }
            // term-outermost: 8 independent MMAs between accumulator reuses
#pragma unroll
            for (int mt = 0; mt < 2; mt++)
#pragma unroll
                for (int nt = 0; nt < 4; nt++)
                    mma_bf16(c[mt][nt], ahi[mt], &bfr[ks][0][nt >> 1][(nt & 1) * 2]);
#pragma unroll
            for (int mt = 0; mt < 2; mt++)
#pragma unroll
                for (int nt = 0; nt < 4; nt++)
                    mma_bf16(c[mt][nt], alo[mt], &bfr[ks][0][nt >> 1][(nt & 1) * 2]);
#pragma unroll
            for (int mt = 0; mt < 2; mt++)
#pragma unroll
                for (int nt = 0; nt < 4; nt++)
                    mma_bf16(c[mt][nt], ahi[mt], &bfr[ks][1][nt >> 1][(nt & 1) * 2]);
        }
    }

    CP_WAIT(0);
    __syncthreads();

    // ---- stage C into smem (overlays stage space) ----
    float (*C)[BN] = (float (*)[BN])dsm;
#pragma unroll
    for (int mt = 0; mt < 2; mt++)
#pragma unroll
        for (int nt = 0; nt < 4; nt++) {
            const int r0 = m_base + mt * 16 + (lane >> 2);
            const int c0 = n_base + nt * 8 + 2 * (lane & 3);
            *(float2*)&C[r0][c0]     = make_float2(c[mt][nt][0], c[mt][nt][1]);
            *(float2*)&C[r0 + 8][c0] = make_float2(c[mt][nt][2], c[mt][nt][3]);
        }
    __syncthreads();

    // ---- epilogue: per-row L2 norm per expert half, GELU, gated combine ----
    const float g0 = g_gate[0], g1 = g_gate[1];
#pragma unroll
    for (int r = 0; r < 8; r++) {
        const int row = wid * 8 + r;
        const float z0a = C[row][lane];
        const float z0b = C[row][lane + 32];
        const float z1a = C[row][64 + lane];
        const float z1b = C[row][96 + lane];
        float ss0 = z0a * z0a + z0b * z0b;
        float ss1 = z1a * z1a + z1b * z1b;
#pragma unroll
        for (int off = 16; off; off >>= 1) {
            ss0 += __shfl_xor_sync(0xffffffffu, ss0, off);
            ss1 += __shfl_xor_sync(0xffffffffu, ss1, off);
        }
        const float inv0 = 1.f / fmaxf(sqrtf(ss0), 1e-12f);
        const float inv1 = 1.f / fmaxf(sqrtf(ss1), 1e-12f);
        float* orow = out + (size_t)(row0 + row) * L_;
        orow[lane]      = g0 * gelu_exact(z0a * inv0) + g1 * gelu_exact(z1a * inv1);
        orow[lane + 32] = g0 * gelu_exact(z0b * inv0) + g1 * gelu_exact(z1b * inv1);
    }
}

// ===========================================================================
extern "C" void kernel_launch(void* const* d_in, const int* in_sizes, int n_in,
                              void* d_out, int out_size) {
    const float* x      = (const float*)d_in[0];
    const float* Wg_in  = (const float*)d_in[1];
    const float* Wg_lin = (const float*)d_in[2];
    const float* Wg_out = (const float*)d_in[3];
    const float* We     = (const float*)d_in[4];
    float* out = (float*)d_out;

    cudaFuncSetAttribute(k_expert, cudaFuncAttributeMaxDynamicSharedMemorySize, SMEM_DYN);

    k_colsum_split<<<NPART, 256>>>(x, Wg_out);
    k_vreduce<<<8, 256>>>();
    k_gate<<<1, 512>>>(Wg_in, Wg_lin);
    k_wsplit<<<128, 256>>>(We);
    k_expert<<<S_ / BM, 256, SMEM_DYN>>>(out);
}

// round 13
// speedup vs baseline: 1.1171x; 1.0731x over previous
#include <cuda_runtime.h>
#include <cuda_fp16.h>
#include <math.h>
#include <stdint.h>

// Problem constants
#define S_ 8192
#define D_ 2048
#define H_ 64
#define E_ 64
#define L_ 64

#define NPART 256          // colsum partial blocks (32 rows each)
#define BM 64
#define BN 128
#define KC 32
#define NCH (D_ / KC)      // 64
#define NKK (D_ / 16)      // 128 k-steps of 16
#define RS 40              // smem row stride in fp16 (80 B, conflict-free ldsm)
#define NSTAGE 8

// dynamic smem stage layout (bytes): A only (hi + lo)
#define AHI_OFF 0
#define ALO_OFF 5120
#define STAGE_BYTES 10240
#define SMEM_DYN (NSTAGE * STAGE_BYTES)   // 81920 (>= 32KB C overlay)

// Static device scratch
__device__ __align__(16) float g_vpart[NPART][D_];
__device__ __align__(16) float g_v[D_];
__device__ float g_gate[2];
__device__ int   g_idx[2];
__device__ __align__(16) uint16_t g_xhi[S_][D_];   // 32 MB (fp16 hi part of x)
__device__ __align__(16) uint16_t g_xlo[S_][D_];   // 32 MB (fp16 lo residual)
// B (w_hi only) in MMA-fragment layout: [kk 128][warp_n 4][nn 2][lane 32] x uint4
__device__ uint4 g_wfrag[NKK * 4 * 2 * 32];        // 512 KB

__device__ __forceinline__ int wf_idx(int kk, int wn, int nn) {
    return (((kk << 2) + wn) * 2 + nn) << 5;
}

// ===========================================================================
// helpers
// ===========================================================================
__device__ __forceinline__ uint32_t smem_u32(const void* p) {
    uint32_t a;
    asm("{ .reg .u64 t; cvta.to.shared.u64 t, %1; cvt.u32.u64 %0, t; }"
        : "=r"(a) : "l"(p));
    return a;
}

__device__ __forceinline__ void cp16(uint32_t dst, const void* src) {
    asm volatile("cp.async.cg.shared.global [%0], [%1], 16;"
                 :: "r"(dst), "l"(src) : "memory");
}
#define CP_COMMIT() asm volatile("cp.async.commit_group;" ::: "memory")
#define CP_WAIT(n)  asm volatile("cp.async.wait_group %0;" :: "n"(n) : "memory")

// fp16 hi/lo split of 2 floats: hi = rn_f16(f), lo = rn_f16(f - hi).
// Packed half2, lower k index in the low half. x = hi + lo exact to ~2^-22.
__device__ __forceinline__ void cvt_split_f16(float f0, float f1,
                                              uint32_t& hi, uint32_t& lo) {
    const __half2 h = __floats2half2_rn(f0, f1);
    const float2 hf = __half22float2(h);
    const __half2 l = __floats2half2_rn(f0 - hf.x, f1 - hf.y);
    hi = *(const uint32_t*)&h;
    lo = *(const uint32_t*)&l;
}

__device__ __forceinline__ void ldsm4(uint32_t* r, uint32_t addr) {
    asm volatile("ldmatrix.sync.aligned.m8n8.x4.shared.b16 {%0,%1,%2,%3}, [%4];"
                 : "=r"(r[0]), "=r"(r[1]), "=r"(r[2]), "=r"(r[3]) : "r"(addr));
}

__device__ __forceinline__ void mma_f16(float* c, const uint32_t* a, const uint32_t* b) {
    asm volatile("mma.sync.aligned.m16n8k16.row.col.f32.f16.f16.f32 "
                 "{%0,%1,%2,%3}, {%4,%5,%6,%7}, {%8,%9}, {%0,%1,%2,%3};"
                 : "+f"(c[0]), "+f"(c[1]), "+f"(c[2]), "+f"(c[3])
                 : "r"(a[0]), "r"(a[1]), "r"(a[2]), "r"(a[3]), "r"(b[0]), "r"(b[1]));
}

__device__ __forceinline__ float gelu_exact(float v) {
    return 0.5f * v * (1.f + erff(v * 0.70710678118654752440f));
}

// ===========================================================================
// Kernel 1: fused weighted column-sum partials + fp16 hi/lo split of x.
// 256 blocks x 32 rows.
// ===========================================================================
__global__ void __launch_bounds__(256) k_colsum_split(const float* __restrict__ x,
                                                      const float* __restrict__ wout) {
    __shared__ float ws[32];
    const int b = blockIdx.x, t = threadIdx.x;
    const int row0 = b * 32;
    if (t < 32) ws[t] = wout[row0 + t];
    __syncthreads();

    const int d0 = t * 8;
    float acc[8];
#pragma unroll
    for (int i = 0; i < 8; i++) acc[i] = 0.f;
    const float* xp = x + (size_t)row0 * D_ + d0;
#pragma unroll 4
    for (int r = 0; r < 32; r++) {
        const float w = ws[r];
        const float4 a = *(const float4*)(xp);
        const float4 c = *(const float4*)(xp + 4);
        acc[0] = fmaf(w, a.x, acc[0]); acc[1] = fmaf(w, a.y, acc[1]);
        acc[2] = fmaf(w, a.z, acc[2]); acc[3] = fmaf(w, a.w, acc[3]);
        acc[4] = fmaf(w, c.x, acc[4]); acc[5] = fmaf(w, c.y, acc[5]);
        acc[6] = fmaf(w, c.z, acc[6]); acc[7] = fmaf(w, c.w, acc[7]);
        uint4 hi, lo;
        cvt_split_f16(a.x, a.y, hi.x, lo.x);
        cvt_split_f16(a.z, a.w, hi.y, lo.y);
        cvt_split_f16(c.x, c.y, hi.z, lo.z);
        cvt_split_f16(c.z, c.w, hi.w, lo.w);
        *(uint4*)&g_xhi[row0 + r][d0] = hi;
        *(uint4*)&g_xlo[row0 + r][d0] = lo;
        xp += D_;
    }
#pragma unroll
    for (int i = 0; i < 8; i++) g_vpart[b][d0 + i] = acc[i];
}

// ===========================================================================
// Kernel 2a: v[d] = sum_b vpart[b][d]
// ===========================================================================
__global__ void __launch_bounds__(256) k_vreduce() {
    const int d = blockIdx.x * 256 + threadIdx.x;
    float s = 0.f;
#pragma unroll 8
    for (int b = 0; b < NPART; b++) s += g_vpart[b][d];
    g_v[d] = s;
}

// ===========================================================================
// Kernel 2b: fused gate: u = Wg_in@v; scores = Wg_lin@u; top-2; softmax.
// ===========================================================================
__global__ void __launch_bounds__(512) k_gate(const float* __restrict__ Wg_in,
                                              const float* __restrict__ Wg_lin) {
    __shared__ float v[D_];
    __shared__ float u[H_];
    __shared__ float sc[E_];
    const int t = threadIdx.x;
    for (int d = t; d < D_; d += 512) v[d] = g_v[d];
    __syncthreads();

    const int wid = t >> 5, lane = t & 31;
#pragma unroll
    for (int jj = 0; jj < 4; jj++) {
        const int j = wid * 4 + jj;
        const float* wr = Wg_in + (size_t)j * D_;
        float s = 0.f;
#pragma unroll
        for (int i = 0; i < 16; i++) {
            const float4 w = *(const float4*)(wr + i * 128 + lane * 4);
            const float4 vv = *(const float4*)(&v[i * 128 + lane * 4]);
            s += w.x * vv.x + w.y * vv.y + w.z * vv.z + w.w * vv.w;
        }
#pragma unroll
        for (int off = 16; off; off >>= 1) s += __shfl_down_sync(0xffffffffu, s, off);
        if (lane == 0) u[j] = s;
    }
    __syncthreads();

    if (t < E_) {
        float s = 0.f;
#pragma unroll
        for (int j = 0; j < H_; j++) s = fmaf(Wg_lin[t * H_ + j], u[j], s);
        sc[t] = s;
    }
    __syncthreads();

    if (t == 0) {
        int i0 = 0;
        for (int e = 1; e < E_; e++) if (sc[e] > sc[i0]) i0 = e;
        int i1 = (i0 == 0) ? 1 : 0;
        for (int e = 0; e < E_; e++) {
            if (e == i0 || e == i1) continue;
            if (sc[e] > sc[i1]) i1 = e;
        }
        const float e1 = expf(sc[i1] - sc[i0]);
        const float inv = 1.f / (1.f + e1);
        g_gate[0] = inv; g_gate[1] = e1 * inv;
        g_idx[0] = i0; g_idx[1] = i1;
    }
}

// ===========================================================================
// Kernel 2c: quantize the two selected experts' weights to fp16 (w_hi only)
// DIRECTLY into MMA fragment layout. Fragment semantics match ldmatrix
// m8n8.x4: thread l holds rows l>>2, cols 2(l&3), 2(l&3)+1 (+8 second reg).
// grid 128 x 256.
// ===========================================================================
__global__ void __launch_bounds__(256) k_wsplit(const float* __restrict__ We) {
    const int item = blockIdx.x * 256 + threadIdx.x;   // 0..32767
    const int lane = item & 31;
    const int nn   = (item >> 5) & 1;
    const int nt32 = (item >> 6) & 3;
    const int kk   = item >> 8;                         // 0..127

    uint4 hi;
#pragma unroll
    for (int j = 0; j < 2; j++) {
        const int n8t = nt32 * 4 + nn * 2 + j;          // 0..15
        const int e = g_idx[n8t >> 3];
        const int nrow = (n8t * 8 + (lane >> 2)) & 63;
        const float* src = We + ((size_t)e * L_ + nrow) * D_ + kk * 16 + 2 * (lane & 3);
        const __half2 h0 = __floats2half2_rn(src[0], src[1]);
        const __half2 h1 = __floats2half2_rn(src[8], src[9]);
        if (j == 0) { hi.x = *(const uint32_t*)&h0; hi.y = *(const uint32_t*)&h1; }
        else        { hi.z = *(const uint32_t*)&h0; hi.w = *(const uint32_t*)&h1; }
    }
    g_wfrag[wf_idx(kk, nt32, nn) + lane] = hi;
}

// ===========================================================================
// Kernel 3: HMMA expert GEMM, fp16 2-term split (x_hi + x_lo vs w_hi).
// A via cp.async 8-stage smem pipeline + LDSM; B fragments from global
// (L2-resident, fragment-ordered) in a depth-1 register pipeline.
// 16 MMAs per k-step (was 24). Fused normalize+GELU+combine epilogue.
//   CTA: 64 rows x 128 cols; 8 warps 2x4; warp = 32x32 via m16n8k16.
// ===========================================================================
__global__ void __launch_bounds__(256) k_expert(float* __restrict__ out) {
    extern __shared__ char dsm[];
    const uint32_t sbase = smem_u32(dsm);

    const int t = threadIdx.x;
    const int wid = t >> 5, lane = t & 31;
    const int row0 = blockIdx.x * BM;

    // ---- cp.async load mapping for A (16B segments; 64 rows x 4 segs) ----
    const int arow = t >> 2, aseg = t & 3;
    const uint16_t* gAhi = &g_xhi[row0 + arow][aseg * 8];
    const uint16_t* gAlo = &g_xlo[row0 + arow][aseg * 8];
    const uint32_t adst = (uint32_t)(arow * RS * 2 + aseg * 16);

    // ---- fragment mapping ----
    const int warp_m = wid & 1, warp_n = wid >> 1;
    const int m_base = warp_m * 32, n_base = warp_n * 32;
    const int a_row = m_base + (lane & 15);
    const int a_k = (lane >> 4) << 3;
    const uint32_t fa = (uint32_t)(a_row * RS + a_k) * 2;

    float c[2][4][4];
#pragma unroll
    for (int mt = 0; mt < 2; mt++)
#pragma unroll
        for (int nt = 0; nt < 4; nt++)
#pragma unroll
            for (int r = 0; r < 4; r++) c[mt][nt][r] = 0.f;

    // ---- prologue: prefetch A stages 0..NSTAGE-2 ----
#pragma unroll
    for (int s = 0; s < NSTAGE - 1; s++) {
        const uint32_t sb = sbase + s * STAGE_BYTES;
        cp16(sb + AHI_OFF + adst, gAhi + s * KC);
        cp16(sb + ALO_OFF + adst, gAlo + s * KC);
        CP_COMMIT();
    }

    // ---- B register pipeline: bfr[parity][nn][4] ----
    uint32_t bfr[2][2][4];
#pragma unroll
    for (int nn = 0; nn < 2; nn++)
        *(uint4*)bfr[0][nn] = g_wfrag[wf_idx(0, warp_n, nn) + lane];

#pragma unroll 1
    for (int ch = 0; ch < NCH; ++ch) {
        CP_WAIT(NSTAGE - 2);
        __syncthreads();

        const uint32_t tb = sbase + (ch & (NSTAGE - 1)) * STAGE_BYTES;

        // issue next A chunk into the stage just freed
        const int pf = ch + NSTAGE - 1;
        if (pf < NCH) {
            const uint32_t sb = sbase + (pf & (NSTAGE - 1)) * STAGE_BYTES;
            cp16(sb + AHI_OFF + adst, gAhi + pf * KC);
            cp16(sb + ALO_OFF + adst, gAlo + pf * KC);
        }
        CP_COMMIT();

#pragma unroll
        for (int ks = 0; ks < 2; ks++) {
            const int kk = ch * 2 + ks;
            // prefetch next k-step's B fragments (hidden under MMAs)
            if (kk + 1 < NKK) {
#pragma unroll
                for (int nn = 0; nn < 2; nn++)
                    *(uint4*)bfr[ks ^ 1][nn] =
                        g_wfrag[wf_idx(kk + 1, warp_n, nn) + lane];
            }
            // A fragments for this k-step
            uint32_t ahi[2][4], alo[2][4];
#pragma unroll
            for (int mt = 0; mt < 2; mt++) {
                ldsm4(ahi[mt], tb + AHI_OFF + fa + mt * (16 * RS * 2) + ks * 32);
                ldsm4(alo[mt], tb + ALO_OFF + fa + mt * (16 * RS * 2) + ks * 32);
            }
            // term-outermost: 8 independent MMAs between accumulator reuses
#pragma unroll
            for (int mt = 0; mt < 2; mt++)
#pragma unroll
                for (int nt = 0; nt < 4; nt++)
                    mma_f16(c[mt][nt], ahi[mt], &bfr[ks][nt >> 1][(nt & 1) * 2]);
#pragma unroll
            for (int mt = 0; mt < 2; mt++)
#pragma unroll
                for (int nt = 0; nt < 4; nt++)
                    mma_f16(c[mt][nt], alo[mt], &bfr[ks][nt >> 1][(nt & 1) * 2]);
        }
    }

    CP_WAIT(0);
    __syncthreads();

    // ---- stage C into smem (overlays stage space) ----
    float (*C)[BN] = (float (*)[BN])dsm;
#pragma unroll
    for (int mt = 0; mt < 2; mt++)
#pragma unroll
        for (int nt = 0; nt < 4; nt++) {
            const int r0 = m_base + mt * 16 + (lane >> 2);
            const int c0 = n_base + nt * 8 + 2 * (lane & 3);
            *(float2*)&C[r0][c0]     = make_float2(c[mt][nt][0], c[mt][nt][1]);
            *(float2*)&C[r0 + 8][c0] = make_float2(c[mt][nt][2], c[mt][nt][3]);
        }
    __syncthreads();

    // ---- epilogue: per-row L2 norm per expert half, GELU, gated combine ----
    const float g0 = g_gate[0], g1 = g_gate[1];
#pragma unroll
    for (int r = 0; r < 8; r++) {
        const int row = wid * 8 + r;
        const float z0a = C[row][lane];
        const float z0b = C[row][lane + 32];
        const float z1a = C[row][64 + lane];
        const float z1b = C[row][96 + lane];
        float ss0 = z0a * z0a + z0b * z0b;
        float ss1 = z1a * z1a + z1b * z1b;
#pragma unroll
        for (int off = 16; off; off >>= 1) {
            ss0 += __shfl_xor_sync(0xffffffffu, ss0, off);
            ss1 += __shfl_xor_sync(0xffffffffu, ss1, off);
        }
        const float inv0 = 1.f / fmaxf(sqrtf(ss0), 1e-12f);
        const float inv1 = 1.f / fmaxf(sqrtf(ss1), 1e-12f);
        float* orow = out + (size_t)(row0 + row) * L_;
        orow[lane]      = g0 * gelu_exact(z0a * inv0) + g1 * gelu_exact(z1a * inv1);
        orow[lane + 32] = g0 * gelu_exact(z0b * inv0) + g1 * gelu_exact(z1b * inv1);
    }
}

// ===========================================================================
extern "C" void kernel_launch(void* const* d_in, const int* in_sizes, int n_in,
                              void* d_out, int out_size) {
    const float* x      = (const float*)d_in[0];
    const float* Wg_in  = (const float*)d_in[1];
    const float* Wg_lin = (const float*)d_in[2];
    const float* Wg_out = (const float*)d_in[3];
    const float* We     = (const float*)d_in[4];
    float* out = (float*)d_out;

    cudaFuncSetAttribute(k_expert, cudaFuncAttributeMaxDynamicSharedMemorySize, SMEM_DYN);

    k_colsum_split<<<NPART, 256>>>(x, Wg_out);
    k_vreduce<<<8, 256>>>();
    k_gate<<<1, 512>>>(Wg_in, Wg_lin);
    k_wsplit<<<128, 256>>>(We);
    k_expert<<<S_ / BM, 256, SMEM_DYN>>>(out);
}

// round 14
// speedup vs baseline: 1.4636x; 1.3102x over previous
#include <cuda_runtime.h>
#include <cuda_fp16.h>
#include <math.h>
#include <stdint.h>

// Problem constants
#define S_ 8192
#define D_ 2048
#define H_ 64
#define E_ 64
#define L_ 64

#define NPART 256          // colsum partial blocks (32 rows each)
#define BM 64
#define BN 128
#define KC 32
#define NCH (D_ / KC)      // 64
#define NKK (D_ / 16)      // 128 k-steps of 16
#define RS 40              // smem row stride in fp16 (80 B, conflict-free ldsm)
#define NSTAGE 8

// dynamic smem stage layout (bytes): A hi only
#define STAGE_BYTES 5120
#define SMEM_DYN (NSTAGE * STAGE_BYTES)   // 40960 (>= 32KB C overlay)

// Static device scratch
__device__ __align__(16) float g_vpart[NPART][D_];
__device__ __align__(16) float g_v[D_];
__device__ float g_gate[2];
__device__ int   g_idx[2];
__device__ __align__(16) uint16_t g_xhi[S_][D_];   // 32 MB (fp16 x)
// B (fp16 w) in MMA-fragment layout: [kk 128][warp_n 4][nn 2][lane 32] x uint4
__device__ uint4 g_wfrag[NKK * 4 * 2 * 32];        // 512 KB

__device__ __forceinline__ int wf_idx(int kk, int wn, int nn) {
    return (((kk << 2) + wn) * 2 + nn) << 5;
}

// ===========================================================================
// helpers
// ===========================================================================
__device__ __forceinline__ uint32_t smem_u32(const void* p) {
    uint32_t a;
    asm("{ .reg .u64 t; cvta.to.shared.u64 t, %1; cvt.u32.u64 %0, t; }"
        : "=r"(a) : "l"(p));
    return a;
}

__device__ __forceinline__ void cp16(uint32_t dst, const void* src) {
    asm volatile("cp.async.cg.shared.global [%0], [%1], 16;"
                 :: "r"(dst), "l"(src) : "memory");
}
#define CP_COMMIT() asm volatile("cp.async.commit_group;" ::: "memory")
#define CP_WAIT(n)  asm volatile("cp.async.wait_group %0;" :: "n"(n) : "memory")

__device__ __forceinline__ void ldsm4(uint32_t* r, uint32_t addr) {
    asm volatile("ldmatrix.sync.aligned.m8n8.x4.shared.b16 {%0,%1,%2,%3}, [%4];"
                 : "=r"(r[0]), "=r"(r[1]), "=r"(r[2]), "=r"(r[3]) : "r"(addr));
}

__device__ __forceinline__ void mma_f16(float* c, const uint32_t* a, const uint32_t* b) {
    asm volatile("mma.sync.aligned.m16n8k16.row.col.f32.f16.f16.f32 "
                 "{%0,%1,%2,%3}, {%4,%5,%6,%7}, {%8,%9}, {%0,%1,%2,%3};"
                 : "+f"(c[0]), "+f"(c[1]), "+f"(c[2]), "+f"(c[3])
                 : "r"(a[0]), "r"(a[1]), "r"(a[2]), "r"(a[3]), "r"(b[0]), "r"(b[1]));
}

__device__ __forceinline__ float gelu_exact(float v) {
    return 0.5f * v * (1.f + erff(v * 0.70710678118654752440f));
}

// ===========================================================================
// Kernel 1: fused weighted column-sum partials + fp16 quantization of x.
// 256 blocks x 32 rows.
// ===========================================================================
__global__ void __launch_bounds__(256) k_colsum_split(const float* __restrict__ x,
                                                      const float* __restrict__ wout) {
    __shared__ float ws[32];
    const int b = blockIdx.x, t = threadIdx.x;
    const int row0 = b * 32;
    if (t < 32) ws[t] = wout[row0 + t];
    __syncthreads();

    const int d0 = t * 8;
    float acc[8];
#pragma unroll
    for (int i = 0; i < 8; i++) acc[i] = 0.f;
    const float* xp = x + (size_t)row0 * D_ + d0;
#pragma unroll 4
    for (int r = 0; r < 32; r++) {
        const float w = ws[r];
        const float4 a = *(const float4*)(xp);
        const float4 c = *(const float4*)(xp + 4);
        acc[0] = fmaf(w, a.x, acc[0]); acc[1] = fmaf(w, a.y, acc[1]);
        acc[2] = fmaf(w, a.z, acc[2]); acc[3] = fmaf(w, a.w, acc[3]);
        acc[4] = fmaf(w, c.x, acc[4]); acc[5] = fmaf(w, c.y, acc[5]);
        acc[6] = fmaf(w, c.z, acc[6]); acc[7] = fmaf(w, c.w, acc[7]);
        uint4 hi;
        const __half2 h0 = __floats2half2_rn(a.x, a.y);
        const __half2 h1 = __floats2half2_rn(a.z, a.w);
        const __half2 h2 = __floats2half2_rn(c.x, c.y);
        const __half2 h3 = __floats2half2_rn(c.z, c.w);
        hi.x = *(const uint32_t*)&h0; hi.y = *(const uint32_t*)&h1;
        hi.z = *(const uint32_t*)&h2; hi.w = *(const uint32_t*)&h3;
        *(uint4*)&g_xhi[row0 + r][d0] = hi;
        xp += D_;
    }
#pragma unroll
    for (int i = 0; i < 8; i++) g_vpart[b][d0 + i] = acc[i];
}

// ===========================================================================
// Kernel 2a: v[d] = sum_b vpart[b][d]
// ===========================================================================
__global__ void __launch_bounds__(256) k_vreduce() {
    const int d = blockIdx.x * 256 + threadIdx.x;
    float s = 0.f;
#pragma unroll 8
    for (int b = 0; b < NPART; b++) s += g_vpart[b][d];
    g_v[d] = s;
}

// ===========================================================================
// Kernel 2b: fused gate: u = Wg_in@v; scores = Wg_lin@u; top-2; softmax.
// ===========================================================================
__global__ void __launch_bounds__(512) k_gate(const float* __restrict__ Wg_in,
                                              const float* __restrict__ Wg_lin) {
    __shared__ float v[D_];
    __shared__ float u[H_];
    __shared__ float sc[E_];
    const int t = threadIdx.x;
    for (int d = t; d < D_; d += 512) v[d] = g_v[d];
    __syncthreads();

    const int wid = t >> 5, lane = t & 31;
#pragma unroll
    for (int jj = 0; jj < 4; jj++) {
        const int j = wid * 4 + jj;
        const float* wr = Wg_in + (size_t)j * D_;
        float s = 0.f;
#pragma unroll
        for (int i = 0; i < 16; i++) {
            const float4 w = *(const float4*)(wr + i * 128 + lane * 4);
            const float4 vv = *(const float4*)(&v[i * 128 + lane * 4]);
            s += w.x * vv.x + w.y * vv.y + w.z * vv.z + w.w * vv.w;
        }
#pragma unroll
        for (int off = 16; off; off >>= 1) s += __shfl_down_sync(0xffffffffu, s, off);
        if (lane == 0) u[j] = s;
    }
    __syncthreads();

    if (t < E_) {
        float s = 0.f;
#pragma unroll
        for (int j = 0; j < H_; j++) s = fmaf(Wg_lin[t * H_ + j], u[j], s);
        sc[t] = s;
    }
    __syncthreads();

    if (t == 0) {
        int i0 = 0;
        for (int e = 1; e < E_; e++) if (sc[e] > sc[i0]) i0 = e;
        int i1 = (i0 == 0) ? 1 : 0;
        for (int e = 0; e < E_; e++) {
            if (e == i0 || e == i1) continue;
            if (sc[e] > sc[i1]) i1 = e;
        }
        const float e1 = expf(sc[i1] - sc[i0]);
        const float inv = 1.f / (1.f + e1);
        g_gate[0] = inv; g_gate[1] = e1 * inv;
        g_idx[0] = i0; g_idx[1] = i1;
    }
}

// ===========================================================================
// Kernel 2c: quantize the two selected experts' weights to fp16 DIRECTLY
// into MMA fragment layout (ldmatrix m8n8.x4 semantics: thread l holds
// rows l>>2, cols 2(l&3), 2(l&3)+1, +8 for the second reg). grid 128 x 256.
// ===========================================================================
__global__ void __launch_bounds__(256) k_wsplit(const float* __restrict__ We) {
    const int item = blockIdx.x * 256 + threadIdx.x;   // 0..32767
    const int lane = item & 31;
    const int nn   = (item >> 5) & 1;
    const int nt32 = (item >> 6) & 3;
    const int kk   = item >> 8;                         // 0..127

    uint4 hi;
#pragma unroll
    for (int j = 0; j < 2; j++) {
        const int n8t = nt32 * 4 + nn * 2 + j;          // 0..15
        const int e = g_idx[n8t >> 3];
        const int nrow = (n8t * 8 + (lane >> 2)) & 63;
        const float* src = We + ((size_t)e * L_ + nrow) * D_ + kk * 16 + 2 * (lane & 3);
        const __half2 h0 = __floats2half2_rn(src[0], src[1]);
        const __half2 h1 = __floats2half2_rn(src[8], src[9]);
        if (j == 0) { hi.x = *(const uint32_t*)&h0; hi.y = *(const uint32_t*)&h1; }
        else        { hi.z = *(const uint32_t*)&h0; hi.w = *(const uint32_t*)&h1; }
    }
    g_wfrag[wf_idx(kk, nt32, nn) + lane] = hi;
}

// ===========================================================================
// Kernel 3: HMMA expert GEMM, pure fp16 (1 term). A via cp.async 8-stage
// smem pipeline + LDSM; B fragments from global (L2-resident, fragment-
// ordered) in a chunk-granular double-buffered register pipeline (next
// chunk's B loaded ~16 MMAs before use -> covers L2 latency).
//   CTA: 64 rows x 128 cols; 8 warps 2x4; warp = 32x32 via m16n8k16.
// ===========================================================================
__global__ void __launch_bounds__(256) k_expert(float* __restrict__ out) {
    extern __shared__ char dsm[];
    const uint32_t sbase = smem_u32(dsm);

    const int t = threadIdx.x;
    const int wid = t >> 5, lane = t & 31;
    const int row0 = blockIdx.x * BM;

    // ---- cp.async load mapping for A (16B segments; 64 rows x 4 segs) ----
    const int arow = t >> 2, aseg = t & 3;
    const uint16_t* gA = &g_xhi[row0 + arow][aseg * 8];
    const uint32_t adst = (uint32_t)(arow * RS * 2 + aseg * 16);

    // ---- fragment mapping ----
    const int warp_m = wid & 1, warp_n = wid >> 1;
    const int m_base = warp_m * 32, n_base = warp_n * 32;
    const int a_row = m_base + (lane & 15);
    const int a_k = (lane >> 4) << 3;
    const uint32_t fa = (uint32_t)(a_row * RS + a_k) * 2;

    float c[2][4][4];
#pragma unroll
    for (int mt = 0; mt < 2; mt++)
#pragma unroll
        for (int nt = 0; nt < 4; nt++)
#pragma unroll
            for (int r = 0; r < 4; r++) c[mt][nt][r] = 0.f;

    // ---- prologue: prefetch A stages 0..NSTAGE-2 ----
#pragma unroll
    for (int s = 0; s < NSTAGE - 1; s++) {
        cp16(sbase + s * STAGE_BYTES + adst, gA + s * KC);
        CP_COMMIT();
    }

    // ---- B register double buffer: cur/nxt[ks][nn][4] ----
    uint32_t cur[2][2][4], nxt[2][2][4];
#pragma unroll
    for (int ks = 0; ks < 2; ks++)
#pragma unroll
        for (int nn = 0; nn < 2; nn++)
            *(uint4*)cur[ks][nn] = g_wfrag[wf_idx(ks, warp_n, nn) + lane];

#pragma unroll 1
    for (int ch = 0; ch < NCH; ++ch) {
        CP_WAIT(NSTAGE - 2);
        __syncthreads();

        const uint32_t tb = sbase + (ch & (NSTAGE - 1)) * STAGE_BYTES;

        // issue next A chunk into the stage just freed
        const int pf = ch + NSTAGE - 1;
        if (pf < NCH) cp16(sbase + (pf & (NSTAGE - 1)) * STAGE_BYTES + adst, gA + pf * KC);
        CP_COMMIT();

        // load NEXT chunk's B fragments now; used after 16 MMAs (~covers L2)
        if (ch + 1 < NCH) {
#pragma unroll
            for (int ks = 0; ks < 2; ks++)
#pragma unroll
                for (int nn = 0; nn < 2; nn++)
                    *(uint4*)nxt[ks][nn] =
                        g_wfrag[wf_idx((ch + 1) * 2 + ks, warp_n, nn) + lane];
        }

#pragma unroll
        for (int ks = 0; ks < 2; ks++) {
            uint32_t a[2][4];
#pragma unroll
            for (int mt = 0; mt < 2; mt++)
                ldsm4(a[mt], tb + fa + mt * (16 * RS * 2) + ks * 32);
            // 8 independent MMAs (each accumulator touched once per k-step)
#pragma unroll
            for (int mt = 0; mt < 2; mt++)
#pragma unroll
                for (int nt = 0; nt < 4; nt++)
                    mma_f16(c[mt][nt], a[mt], &cur[ks][nt >> 1][(nt & 1) * 2]);
        }

        // rotate B buffers (register moves on alu pipe)
#pragma unroll
        for (int ks = 0; ks < 2; ks++)
#pragma unroll
            for (int nn = 0; nn < 2; nn++)
#pragma unroll
                for (int i = 0; i < 4; i++) cur[ks][nn][i] = nxt[ks][nn][i];
    }

    CP_WAIT(0);
    __syncthreads();

    // ---- stage C into smem (overlays stage space) ----
    float (*C)[BN] = (float (*)[BN])dsm;
#pragma unroll
    for (int mt = 0; mt < 2; mt++)
#pragma unroll
        for (int nt = 0; nt < 4; nt++) {
            const int r0 = m_base + mt * 16 + (lane >> 2);
            const int c0 = n_base + nt * 8 + 2 * (lane & 3);
            *(float2*)&C[r0][c0]     = make_float2(c[mt][nt][0], c[mt][nt][1]);
            *(float2*)&C[r0 + 8][c0] = make_float2(c[mt][nt][2], c[mt][nt][3]);
        }
    __syncthreads();

    // ---- epilogue: per-row L2 norm per expert half, GELU, gated combine ----
    const float g0 = g_gate[0], g1 = g_gate[1];
#pragma unroll
    for (int r = 0; r < 8; r++) {
        const int row = wid * 8 + r;
        const float z0a = C[row][lane];
        const float z0b = C[row][lane + 32];
        const float z1a = C[row][64 + lane];
        const float z1b = C[row][96 + lane];
        float ss0 = z0a * z0a + z0b * z0b;
        float ss1 = z1a * z1a + z1b * z1b;
#pragma unroll
        for (int off = 16; off; off >>= 1) {
            ss0 += __shfl_xor_sync(0xffffffffu, ss0, off);
            ss1 += __shfl_xor_sync(0xffffffffu, ss1, off);
        }
        const float inv0 = 1.f / fmaxf(sqrtf(ss0), 1e-12f);
        const float inv1 = 1.f / fmaxf(sqrtf(ss1), 1e-12f);
        float* orow = out + (size_t)(row0 + row) * L_;
        orow[lane]      = g0 * gelu_exact(z0a * inv0) + g1 * gelu_exact(z1a * inv1);
        orow[lane + 32] = g0 * gelu_exact(z0b * inv0) + g1 * gelu_exact(z1b * inv1);
    }
}

// ===========================================================================
extern "C" void kernel_launch(void* const* d_in, const int* in_sizes, int n_in,
                              void* d_out, int out_size) {
    const float* x      = (const float*)d_in[0];
    const float* Wg_in  = (const float*)d_in[1];
    const float* Wg_lin = (const float*)d_in[2];
    const float* Wg_out = (const float*)d_in[3];
    const float* We     = (const float*)d_in[4];
    float* out = (float*)d_out;

    cudaFuncSetAttribute(k_expert, cudaFuncAttributeMaxDynamicSharedMemorySize, SMEM_DYN);

    k_colsum_split<<<NPART, 256>>>(x, Wg_out);
    k_vreduce<<<8, 256>>>();
    k_gate<<<1, 512>>>(Wg_in, Wg_lin);
    k_wsplit<<<128, 256>>>(We);
    k_expert<<<S_ / BM, 256, SMEM_DYN>>>(out);
}